// round 5
// baseline (speedup 1.0000x reference)
#include <cuda_runtime.h>
#include <cstdint>
#include <math.h>

#define TOKENS 8192
#define HIDDEN 7168
#define NEXP   256
#define TOP_K  8

// ---------------- persistent GEMM+route config ------------------------------
#define BM 64
#define BN 64
#define BK 32
#define KHALF (HIDDEN / 2)          // 3584
#define KT_ITERS (KHALF / BK)       // 112 per unit
#define STAGES 3
#define NTHREADS 64
#define NCTAS 592                   // 148 SMs x 4
#define GEMM_UNITS 1024             // 128 m x 4 n x 2 khalf
#define ROUTE_UNITS 4096            // 2 tokens each
#define TOTAL_UNITS (GEMM_UNITS + ROUTE_UNITS)

#define ASTRIDE 36                  // banks (4r+k) all distinct
#define BSTRIDE 72                  // banks (8k+n) all distinct
#define A_FLOATS (BM * ASTRIDE)     // 2304
#define B_FLOATS (BK * BSTRIDE)     // 2304
#define STAGE_FLOATS (A_FLOATS + B_FLOATS)
#define SMEM_DYN (STAGES * STAGE_FLOATS * 4)    // 55296 B -> 4 CTAs/SM

// device scratch (no cudaMalloc allowed)
__device__ float g_part[2][(size_t)TOKENS * NEXP];   // per-k-half partial logits
__device__ unsigned int g_done[TOKENS / BM];         // 128 row-block counters (target 8)
__device__ unsigned int g_unit_counter;

__device__ __forceinline__ uint32_t smem_u32(const void* p) {
    uint32_t a;
    asm("{ .reg .u64 t; cvta.to.shared.u64 t, %1; cvt.u32.u64 %0, t; }" : "=r"(a) : "l"(p));
    return a;
}
__device__ __forceinline__ void cp_async16(uint32_t s, const void* g) {
    asm volatile("cp.async.cg.shared.global [%0], [%1], 16;\n" :: "r"(s), "l"(g));
}
__device__ __forceinline__ void mma_tf32(float* c, const uint32_t* a, const uint32_t* b) {
    asm volatile(
        "mma.sync.aligned.m16n8k8.row.col.f32.tf32.tf32.f32 "
        "{%0,%1,%2,%3}, {%4,%5,%6,%7}, {%8,%9}, {%0,%1,%2,%3};\n"
        : "+f"(c[0]), "+f"(c[1]), "+f"(c[2]), "+f"(c[3])
        : "r"(a[0]), "r"(a[1]), "r"(a[2]), "r"(a[3]), "r"(b[0]), "r"(b[1]));
}
__device__ __forceinline__ unsigned ld_acquire(const unsigned* p) {
    unsigned v;
    asm volatile("ld.acquire.gpu.global.u32 %0, [%1];" : "=r"(v) : "l"(p));
    return v;
}

// ---------------------------------------------------------------------------
__global__ void init_kernel() {
    if (threadIdx.x < TOKENS / BM) g_done[threadIdx.x] = 0u;
    if (threadIdx.x == 0) g_unit_counter = 0u;
}

// ---------------------------------------------------------------------------
// one GEMM work unit: 64x64 tile, half of K
// ---------------------------------------------------------------------------
__device__ void gemm_unit(unsigned u, const float* __restrict__ A,
                          const float* __restrict__ B, float* smem)
{
    const int tid  = threadIdx.x;
    const int wid  = tid >> 5;
    const int lane = tid & 31;

    const int mtile = (int)(u >> 3);
    const int ntile = (int)(u & 3);
    const int kh    = (int)((u >> 2) & 1);
    const int brow  = mtile * BM;
    const int bcol  = ntile * BN;
    const int kbase = kh * KHALF;

    const float* agp[8]; uint32_t aof[8];
    const float* bgp[8]; uint32_t bof[8];
    #pragma unroll
    for (int j = 0; j < 8; j++) {
        int i = tid + j * 64;           // A: 64 rows x 8 chunks of 16B
        int r = i >> 3, c = i & 7;
        aof[j] = (uint32_t)(r * ASTRIDE + c * 4) * 4u;
        agp[j] = A + (size_t)(brow + r) * HIDDEN + kbase + c * 4;
    }
    #pragma unroll
    for (int j = 0; j < 8; j++) {
        int i = tid + j * 64;           // B: 32 rows x 16 chunks of 16B
        int r = i >> 4, c = i & 15;
        bof[j] = (uint32_t)(A_FLOATS + r * BSTRIDE + c * 4) * 4u;
        bgp[j] = B + (size_t)(kbase + r) * NEXP + bcol + c * 4;
    }
    const uint32_t smem_base = smem_u32(smem);

    auto load_stage = [&](int kt) {
        const uint32_t sbase = smem_base + (uint32_t)(kt % STAGES) * (STAGE_FLOATS * 4);
        const int koff = kt * BK;
        #pragma unroll
        for (int j = 0; j < 8; j++) cp_async16(sbase + aof[j], agp[j] + koff);
        #pragma unroll
        for (int j = 0; j < 8; j++) cp_async16(sbase + bof[j], bgp[j] + (size_t)koff * NEXP);
        asm volatile("cp.async.commit_group;\n" ::: "memory");
    };

    float acc[4][4][4];
    #pragma unroll
    for (int mt = 0; mt < 4; mt++)
        #pragma unroll
        for (int nt = 0; nt < 4; nt++)
            #pragma unroll
            for (int i = 0; i < 4; i++) acc[mt][nt][i] = 0.f;

    load_stage(0);
    load_stage(1);

    const int arow0 = lane >> 2;
    const int bcol0 = wid * 32 + (lane >> 2);
    const int ak    = lane & 3;

    for (int kt = 0; kt < KT_ITERS; kt++) {
        if (kt == KT_ITERS - 1)
            asm volatile("cp.async.wait_group 0;\n" ::: "memory");
        else
            asm volatile("cp.async.wait_group 1;\n" ::: "memory");
        __syncthreads();

        if (kt + 2 < KT_ITERS) load_stage(kt + 2);

        const float* As = smem + (size_t)(kt % STAGES) * STAGE_FLOATS;
        const float* Bs = As + A_FLOATS;

        #pragma unroll
        for (int ks = 0; ks < 4; ks++) {
            const int kk = ks * 8;
            uint32_t afr[4][4];
            uint32_t bfr[4][2];
            #pragma unroll
            for (int mt = 0; mt < 4; mt++) {
                const int m0 = arow0 + mt * 16;
                const int cc = kk + ak;
                afr[mt][0] = __float_as_uint(As[m0 * ASTRIDE + cc]);
                afr[mt][1] = __float_as_uint(As[(m0 + 8) * ASTRIDE + cc]);
                afr[mt][2] = __float_as_uint(As[m0 * ASTRIDE + cc + 4]);
                afr[mt][3] = __float_as_uint(As[(m0 + 8) * ASTRIDE + cc + 4]);
            }
            #pragma unroll
            for (int nt = 0; nt < 4; nt++) {
                const int n0 = bcol0 + nt * 8;
                const int kr = kk + ak;
                bfr[nt][0] = __float_as_uint(Bs[kr * BSTRIDE + n0]);
                bfr[nt][1] = __float_as_uint(Bs[(kr + 4) * BSTRIDE + n0]);
            }
            #pragma unroll
            for (int mt = 0; mt < 4; mt++)
                #pragma unroll
                for (int nt = 0; nt < 4; nt++)
                    mma_tf32(acc[mt][nt], afr[mt], bfr[nt]);
        }
    }

    // epilogue: plain stores to this k-half's partial buffer
    float* dst = g_part[kh];
    #pragma unroll
    for (int mt = 0; mt < 4; mt++) {
        #pragma unroll
        for (int nt = 0; nt < 4; nt++) {
            int row = brow + mt * 16 + (lane >> 2);
            int col = bcol + wid * 32 + nt * 8 + (lane & 3) * 2;
            *(float2*)&dst[(size_t)row * NEXP + col] =
                make_float2(acc[mt][nt][0], acc[mt][nt][1]);
            *(float2*)&dst[(size_t)(row + 8) * NEXP + col] =
                make_float2(acc[mt][nt][2], acc[mt][nt][3]);
        }
    }
    __threadfence();
    __syncthreads();
    if (tid == 0) atomicAdd(&g_done[mtile], 1u);
}

// ---------------------------------------------------------------------------
// one route unit: 2 tokens, one warp per token
// ---------------------------------------------------------------------------
__device__ void route_unit(unsigned ru, const float* __restrict__ bias,
                           float* __restrict__ out)
{
    const int wid   = threadIdx.x >> 5;
    const int lane  = threadIdx.x & 31;
    const int token = (int)(ru * 2) + wid;
    const int rb    = token >> 6;    // 64-token row block

    while (ld_acquire(&g_done[rb]) < 8u) __nanosleep(64);

    const float4* p0 = (const float4*)(g_part[0] + (size_t)token * NEXP + lane * 8);
    const float4* p1 = (const float4*)(g_part[1] + (size_t)token * NEXP + lane * 8);
    float4 a0 = p0[0], a1 = p0[1], b0 = p1[0], b1 = p1[1];

    float s[8];
    {
        float l[8] = { a0.x + b0.x, a0.y + b0.y, a0.z + b0.z, a0.w + b0.w,
                       a1.x + b1.x, a1.y + b1.y, a1.z + b1.z, a1.w + b1.w };
        #pragma unroll
        for (int i = 0; i < 8; i++) {
            float sc = 1.f / (1.f + expf(-l[i]));
            s[i] = sc + __ldg(&bias[lane * 8 + i]);
        }
    }

    // per-lane top-2, then merge across the 4 lanes of the group
    float m1 = -INFINITY, m2 = -INFINITY;
    #pragma unroll
    for (int i = 0; i < 8; i++) {
        float v = s[i];
        if (v > m1) { m2 = m1; m1 = v; }
        else if (v > m2) { m2 = v; }
    }
    #pragma unroll
    for (int off = 1; off <= 2; off <<= 1) {
        float o1 = __shfl_xor_sync(0xffffffffu, m1, off);
        float o2 = __shfl_xor_sync(0xffffffffu, m2, off);
        float hi = fmaxf(m1, o1);
        float lo = fmaxf(fminf(m1, o1), fmaxf(m2, o2));
        m1 = hi; m2 = lo;
    }
    float gsum = m1 + m2;

    float gs[8];
    #pragma unroll
    for (int g = 0; g < 8; g++)
        gs[g] = __shfl_sync(0xffffffffu, gsum, g * 4);

    const int myg = lane >> 2;
    int rank = 0;
    #pragma unroll
    for (int h = 0; h < 8; h++)
        if (gs[h] > gs[myg] || (gs[h] == gs[myg] && h < myg)) rank++;
    const bool sel = rank < 4;

    float vals[8];
    #pragma unroll
    for (int i = 0; i < 8; i++) vals[i] = sel ? s[i] : 0.f;

    float w[TOP_K];
    #pragma unroll
    for (int t = 0; t < TOP_K; t++) {
        float bv = vals[0];
        int bi = 0;
        #pragma unroll
        for (int i = 1; i < 8; i++)
            if (vals[i] > bv) { bv = vals[i]; bi = i; }
        int bidx = lane * 8 + bi;
        #pragma unroll
        for (int off = 16; off >= 1; off >>= 1) {
            float ov = __shfl_xor_sync(0xffffffffu, bv, off);
            int   oi = __shfl_xor_sync(0xffffffffu, bidx, off);
            if (ov > bv || (ov == bv && oi < bidx)) { bv = ov; bidx = oi; }
        }
        w[t] = bv;
        if ((bidx >> 3) == lane) vals[bidx & 7] = -INFINITY;
    }

    float denom = 1e-20f;
    #pragma unroll
    for (int t = 0; t < TOP_K; t++) denom += w[t];
    const float scale = 2.5f / denom;

    if (lane == 0) {
        #pragma unroll
        for (int t = 0; t < TOP_K; t++)
            out[(size_t)token * TOP_K + t] = w[t] * scale;
    }
}

// ---------------------------------------------------------------------------
// persistent kernel: work-stealing over GEMM units then route units
// ---------------------------------------------------------------------------
__global__ __launch_bounds__(NTHREADS, 4) void moe_persistent(
    const float* __restrict__ A, const float* __restrict__ B,
    const float* __restrict__ bias, float* __restrict__ out)
{
    extern __shared__ float smem[];
    __shared__ unsigned s_u;

    for (;;) {
        if (threadIdx.x == 0) s_u = atomicAdd(&g_unit_counter, 1u);
        __syncthreads();
        const unsigned u = s_u;
        __syncthreads();          // protect s_u for next round + smem reuse
        if (u >= TOTAL_UNITS) break;
        if (u < GEMM_UNITS)
            gemm_unit(u, A, B, smem);
        else
            route_unit(u - GEMM_UNITS, bias, out);
    }
}

// ---------------------------------------------------------------------------
extern "C" void kernel_launch(void* const* d_in, const int* in_sizes, int n_in,
                              void* d_out, int out_size)
{
    (void)in_sizes; (void)n_in; (void)out_size;
    const float* hs   = (const float*)d_in[0];  // [8192, 7168]
    const float* W    = (const float*)d_in[1];  // [7168, 256]
    const float* bias = (const float*)d_in[2];  // [256]
    float* out = (float*)d_out;                 // [8192, 8]

    cudaFuncSetAttribute(moe_persistent, cudaFuncAttributeMaxDynamicSharedMemorySize, SMEM_DYN);

    init_kernel<<<1, 128>>>();
    moe_persistent<<<NCTAS, NTHREADS, SMEM_DYN>>>(hs, W, bias, out);
}